// round 2
// baseline (speedup 1.0000x reference)
#include <cuda_runtime.h>
#include <math.h>

#define BB 2
#define SS 2048
#define HH 16
#define DK 64
#define DM 1024
#define NQ (BB*SS)
#define INV_T 0.125f
#define NEGV -1000000000.0f

// ---------------- scratch (static device allocations only) ----------------
__device__ float g_q[(size_t)BB*HH*SS*DK];
__device__ float g_k[(size_t)BB*HH*SS*DK];
__device__ float g_v[(size_t)BB*HH*SS*DK];
__device__ float g_o[(size_t)NQ*DM];
__device__ float g_tmp[(size_t)NQ*DM];
__device__ float g_m[(size_t)BB*HH*SS];
__device__ float g_l[(size_t)BB*HH*SS];
__device__ float g_attn_fb[(size_t)BB*HH*SS*SS];   // fallback if attn not in d_out

// ---------------- QKV projection GEMM: C = X @ W, stored head-major -------
// X: [4096,1024] row-major, W: [1024,1024] row-major.
// out_head[((b*H+h)*S+s)*64 + d]  with col c = h*64+d, row r = b*S+s
__global__ __launch_bounds__(256) void gemm_proj(const float* __restrict__ X,
                                                 const float* __restrict__ W,
                                                 float* __restrict__ outh)
{
    __shared__ float As[16][68];
    __shared__ float Bs[16][68];
    int tid = threadIdx.x;
    int ty = tid >> 4, tx = tid & 15;
    int row0 = blockIdx.y * 64, col0 = blockIdx.x * 64;
    float acc[4][4] = {};
    for (int k0 = 0; k0 < DM; k0 += 16) {
        {   // A tile 64x16, one float4 per thread
            int r = tid >> 2, kq = (tid & 3) * 4;
            float4 v = *(const float4*)&X[(size_t)(row0 + r)*DM + k0 + kq];
            As[kq+0][r]=v.x; As[kq+1][r]=v.y; As[kq+2][r]=v.z; As[kq+3][r]=v.w;
        }
        {   // B tile 16x64
            int kr = tid >> 4, cq = (tid & 15) * 4;
            float4 v = *(const float4*)&W[(size_t)(k0 + kr)*DM + col0 + cq];
            *(float4*)&Bs[kr][cq] = v;
        }
        __syncthreads();
        #pragma unroll
        for (int kk = 0; kk < 16; kk++) {
            float a[4], b[4];
            #pragma unroll
            for (int i = 0; i < 4; i++) a[i] = As[kk][ty*4+i];
            #pragma unroll
            for (int j = 0; j < 4; j++) b[j] = Bs[kk][tx*4+j];
            #pragma unroll
            for (int i = 0; i < 4; i++)
                #pragma unroll
                for (int j = 0; j < 4; j++) acc[i][j] = fmaf(a[i], b[j], acc[i][j]);
        }
        __syncthreads();
    }
    int c = col0 + tx*4;
    int h = c >> 6, d = c & 63;
    #pragma unroll
    for (int i = 0; i < 4; i++) {
        int r = row0 + ty*4 + i;
        int b = r / SS, s = r % SS;
        *(float4*)&outh[(((size_t)b*HH + h)*SS + s)*DK + d] =
            make_float4(acc[i][0], acc[i][1], acc[i][2], acc[i][3]);
    }
}

// ---------------- fc GEMM + residual: tmp = O @ Wfc + qkv ----------------
__global__ __launch_bounds__(256) void gemm_fc(const float* __restrict__ X,
                                               const float* __restrict__ W,
                                               const float* __restrict__ resid,
                                               float* __restrict__ out)
{
    __shared__ float As[16][68];
    __shared__ float Bs[16][68];
    int tid = threadIdx.x;
    int ty = tid >> 4, tx = tid & 15;
    int row0 = blockIdx.y * 64, col0 = blockIdx.x * 64;
    float acc[4][4] = {};
    for (int k0 = 0; k0 < DM; k0 += 16) {
        {
            int r = tid >> 2, kq = (tid & 3) * 4;
            float4 v = *(const float4*)&X[(size_t)(row0 + r)*DM + k0 + kq];
            As[kq+0][r]=v.x; As[kq+1][r]=v.y; As[kq+2][r]=v.z; As[kq+3][r]=v.w;
        }
        {
            int kr = tid >> 4, cq = (tid & 15) * 4;
            float4 v = *(const float4*)&W[(size_t)(k0 + kr)*DM + col0 + cq];
            *(float4*)&Bs[kr][cq] = v;
        }
        __syncthreads();
        #pragma unroll
        for (int kk = 0; kk < 16; kk++) {
            float a[4], b[4];
            #pragma unroll
            for (int i = 0; i < 4; i++) a[i] = As[kk][ty*4+i];
            #pragma unroll
            for (int j = 0; j < 4; j++) b[j] = Bs[kk][tx*4+j];
            #pragma unroll
            for (int i = 0; i < 4; i++)
                #pragma unroll
                for (int j = 0; j < 4; j++) acc[i][j] = fmaf(a[i], b[j], acc[i][j]);
        }
        __syncthreads();
    }
    #pragma unroll
    for (int i = 0; i < 4; i++) {
        int r = row0 + ty*4 + i;
        int c = col0 + tx*4;
        float4 rv = *(const float4*)&resid[(size_t)r*DM + c];
        *(float4*)&out[(size_t)r*DM + c] =
            make_float4(acc[i][0]+rv.x, acc[i][1]+rv.y, acc[i][2]+rv.z, acc[i][3]+rv.w);
    }
}

// -------- pass 1: raw masked/scaled scores -> attn buf; online m,l -------
__global__ __launch_bounds__(256) void attn_scores(
    const float* __restrict__ qb, const float* __restrict__ kb,
    const int* __restrict__ mask, float* __restrict__ attn,
    float* __restrict__ gm, float* __restrict__ gl)
{
    __shared__ float Qs[64][65];
    __shared__ float Ks[64][65];
    __shared__ float m_s[64];
    __shared__ float l_s[64];
    int tid = threadIdx.x;
    int ty = tid >> 4, tx = tid & 15;
    int q0 = blockIdx.x * 64;
    int bh = blockIdx.y;
    int b = bh >> 4;
    const float* qbase = qb + ((size_t)bh*SS + q0) * DK;
    #pragma unroll
    for (int k = 0; k < 4; k++) {           // Q tile, transposed: Qs[d][r]
        int p = tid + k*256;
        int r = p >> 4, d4 = (p & 15) * 4;
        float4 v = *(const float4*)&qbase[(size_t)r*DK + d4];
        Qs[d4+0][r]=v.x; Qs[d4+1][r]=v.y; Qs[d4+2][r]=v.z; Qs[d4+3][r]=v.w;
    }
    if (tid < 64) { m_s[tid] = -INFINITY; l_s[tid] = 0.0f; }
    int r0 = ty*4, c0 = tx*4;
    for (int kt = 0; kt < SS/64; kt++) {
        int k0 = kt * 64;
        __syncthreads();                    // protect Ks overwrite + m_s reads
        const float* kbase = kb + ((size_t)bh*SS + k0) * DK;
        #pragma unroll
        for (int k = 0; k < 4; k++) {       // K tile, transposed: Ks[d][c]
            int p = tid + k*256;
            int r = p >> 4, d4 = (p & 15) * 4;
            float4 v = *(const float4*)&kbase[(size_t)r*DK + d4];
            Ks[d4+0][r]=v.x; Ks[d4+1][r]=v.y; Ks[d4+2][r]=v.z; Ks[d4+3][r]=v.w;
        }
        __syncthreads();
        float acc[4][4] = {};
        #pragma unroll
        for (int d = 0; d < 64; d++) {
            float a[4], bb[4];
            #pragma unroll
            for (int i = 0; i < 4; i++) a[i] = Qs[d][r0+i];
            #pragma unroll
            for (int j = 0; j < 4; j++) bb[j] = Ks[d][c0+j];
            #pragma unroll
            for (int i = 0; i < 4; i++)
                #pragma unroll
                for (int j = 0; j < 4; j++) acc[i][j] = fmaf(a[i], bb[j], acc[i][j]);
        }
        float rm[4];
        #pragma unroll
        for (int i = 0; i < 4; i++) {       // scale + mask-replace + write raw
            int q = q0 + r0 + i;
            const int4 mv = *(const int4*)&mask[((size_t)b*SS + q)*SS + k0 + c0];
            acc[i][0] = mv.x ? acc[i][0]*INV_T : NEGV;
            acc[i][1] = mv.y ? acc[i][1]*INV_T : NEGV;
            acc[i][2] = mv.z ? acc[i][2]*INV_T : NEGV;
            acc[i][3] = mv.w ? acc[i][3]*INV_T : NEGV;
            *(float4*)&attn[((size_t)bh*SS + q)*SS + k0 + c0] =
                make_float4(acc[i][0], acc[i][1], acc[i][2], acc[i][3]);
            rm[i] = fmaxf(fmaxf(acc[i][0], acc[i][1]), fmaxf(acc[i][2], acc[i][3]));
        }
        #pragma unroll
        for (int o = 1; o < 16; o <<= 1)
            #pragma unroll
            for (int i = 0; i < 4; i++)
                rm[i] = fmaxf(rm[i], __shfl_xor_sync(0xffffffffu, rm[i], o));
        float m_old[4] = {0,0,0,0};
        if (tx == 0) {
            #pragma unroll
            for (int i = 0; i < 4; i++) {
                m_old[i] = m_s[r0+i];
                m_s[r0+i] = fmaxf(m_old[i], rm[i]);
            }
        }
        __syncthreads();
        float ps[4];
        #pragma unroll
        for (int i = 0; i < 4; i++) {
            float mr = m_s[r0+i];
            ps[i] = __expf(acc[i][0]-mr) + __expf(acc[i][1]-mr)
                  + __expf(acc[i][2]-mr) + __expf(acc[i][3]-mr);
        }
        #pragma unroll
        for (int o = 1; o < 16; o <<= 1)
            #pragma unroll
            for (int i = 0; i < 4; i++)
                ps[i] += __shfl_xor_sync(0xffffffffu, ps[i], o);
        if (tx == 0) {
            #pragma unroll
            for (int i = 0; i < 4; i++) {
                float mn = m_s[r0+i];
                l_s[r0+i] = l_s[r0+i]*__expf(m_old[i]-mn) + ps[i];
            }
        }
    }
    __syncthreads();
    if (tid < 64) {
        gm[(size_t)bh*SS + q0 + tid] = m_s[tid];
        gl[(size_t)bh*SS + q0 + tid] = l_s[tid];
    }
}

// -------- pass 2: normalize attn in place, O = P @ V (head-merged) -------
__global__ __launch_bounds__(256) void attn_av(
    const float* __restrict__ vb, float* __restrict__ attn,
    const float* __restrict__ gm, const float* __restrict__ gl,
    float* __restrict__ ob)
{
    __shared__ float Ps[64][65];
    __shared__ float Vs[64][68];
    __shared__ float m_s[64], li_s[64];
    int tid = threadIdx.x;
    int ty = tid >> 4, tx = tid & 15;
    int q0 = blockIdx.x * 64, bh = blockIdx.y;
    int b = bh >> 4, h = bh & 15;
    if (tid < 64) {
        m_s[tid]  = gm[(size_t)bh*SS + q0 + tid];
        li_s[tid] = 1.0f / gl[(size_t)bh*SS + q0 + tid];
    }
    int r0 = ty*4, c0 = tx*4;
    float acc[4][4] = {};
    for (int kt = 0; kt < SS/64; kt++) {
        int k0 = kt * 64;
        __syncthreads();
        #pragma unroll
        for (int k = 0; k < 4; k++) {       // load raw, exp-normalize, write back
            int p = tid + k*256;
            int r = p >> 4, c4 = (p & 15) * 4;
            float* ap = &attn[((size_t)bh*SS + q0 + r)*SS + k0 + c4];
            float4 v = *(float4*)ap;
            float mr = m_s[r], li = li_s[r];
            v.x = __expf(v.x - mr) * li;
            v.y = __expf(v.y - mr) * li;
            v.z = __expf(v.z - mr) * li;
            v.w = __expf(v.w - mr) * li;
            *(float4*)ap = v;
            Ps[c4+0][r]=v.x; Ps[c4+1][r]=v.y; Ps[c4+2][r]=v.z; Ps[c4+3][r]=v.w;
        }
        const float* vbase = vb + ((size_t)bh*SS + k0) * DK;
        #pragma unroll
        for (int k = 0; k < 4; k++) {       // V tile natural layout Vs[c][d]
            int p = tid + k*256;
            int r = p >> 4, d4 = (p & 15) * 4;
            *(float4*)&Vs[r][d4] = *(const float4*)&vbase[(size_t)r*DK + d4];
        }
        __syncthreads();
        #pragma unroll
        for (int c = 0; c < 64; c++) {
            float pv[4], vv[4];
            #pragma unroll
            for (int i = 0; i < 4; i++) pv[i] = Ps[c][r0+i];
            #pragma unroll
            for (int j = 0; j < 4; j++) vv[j] = Vs[c][c0+j];
            #pragma unroll
            for (int i = 0; i < 4; i++)
                #pragma unroll
                for (int j = 0; j < 4; j++) acc[i][j] = fmaf(pv[i], vv[j], acc[i][j]);
        }
    }
    #pragma unroll
    for (int i = 0; i < 4; i++) {
        int q = q0 + r0 + i;
        *(float4*)&ob[((size_t)(b*SS + q))*DM + h*DK + c0] =
            make_float4(acc[i][0], acc[i][1], acc[i][2], acc[i][3]);
    }
}

// ---------------- LayerNorm: one row (1024) per block --------------------
__global__ __launch_bounds__(256) void ln_kernel(const float* __restrict__ xin,
                                                 const float* __restrict__ gamma,
                                                 const float* __restrict__ beta,
                                                 float* __restrict__ out)
{
    __shared__ float red[8];
    __shared__ float mu_s, rs_s;
    int row = blockIdx.x, tid = threadIdx.x;
    float4 v = *(const float4*)&xin[(size_t)row*DM + tid*4];
    float s = v.x + v.y + v.z + v.w;
    #pragma unroll
    for (int o = 16; o > 0; o >>= 1) s += __shfl_down_sync(0xffffffffu, s, o);
    if ((tid & 31) == 0) red[tid >> 5] = s;
    __syncthreads();
    if (tid == 0) {
        float t = 0;
        #pragma unroll
        for (int i = 0; i < 8; i++) t += red[i];
        mu_s = t * (1.0f / DM);
    }
    __syncthreads();
    float mu = mu_s;
    float dx0 = v.x-mu, dx1 = v.y-mu, dx2 = v.z-mu, dx3 = v.w-mu;
    float s2 = dx0*dx0 + dx1*dx1 + dx2*dx2 + dx3*dx3;
    #pragma unroll
    for (int o = 16; o > 0; o >>= 1) s2 += __shfl_down_sync(0xffffffffu, s2, o);
    if ((tid & 31) == 0) red[tid >> 5] = s2;
    __syncthreads();
    if (tid == 0) {
        float t = 0;
        #pragma unroll
        for (int i = 0; i < 8; i++) t += red[i];
        rs_s = rsqrtf(t * (1.0f / DM) + 1e-6f);
    }
    __syncthreads();
    float rs = rs_s;
    float4 g  = *(const float4*)&gamma[tid*4];
    float4 bt = *(const float4*)&beta[tid*4];
    float4 o4;
    o4.x = dx0*rs*g.x + bt.x;
    o4.y = dx1*rs*g.y + bt.y;
    o4.z = dx2*rs*g.z + bt.z;
    o4.w = dx3*rs*g.w + bt.w;
    *(float4*)&out[(size_t)row*DM + tid*4] = o4;
}

// --------------------------------------------------------------------------
extern "C" void kernel_launch(void* const* d_in, const int* in_sizes, int n_in,
                              void* d_out, int out_size)
{
    const float* qkv   = (const float*)d_in[0];
    const int*   mask  = (const int*)  d_in[1];
    const float* w_qs  = (const float*)d_in[2];
    const float* w_ks  = (const float*)d_in[3];
    const float* w_vs  = (const float*)d_in[4];
    const float* w_fc  = (const float*)d_in[5];
    const float* gamma = (const float*)d_in[6];
    const float* beta  = (const float*)d_in[7];
    float* out = (float*)d_out;

    const size_t out_elems  = (size_t)NQ * DM;                 // 4,194,304
    const size_t attn_elems = (size_t)BB * HH * SS * SS;       // 134,217,728

    float *qb, *kb, *vb, *ob, *tb, *mb, *lb, *attn;
    cudaGetSymbolAddress((void**)&qb, g_q);
    cudaGetSymbolAddress((void**)&kb, g_k);
    cudaGetSymbolAddress((void**)&vb, g_v);
    cudaGetSymbolAddress((void**)&ob, g_o);
    cudaGetSymbolAddress((void**)&tb, g_tmp);
    cudaGetSymbolAddress((void**)&mb, g_m);
    cudaGetSymbolAddress((void**)&lb, g_l);
    if ((size_t)out_size >= out_elems + attn_elems) {
        attn = out + out_elems;          // attn is part of the output
    } else {
        cudaGetSymbolAddress((void**)&attn, g_attn_fb);
    }

    dim3 ggrid(DM/64, NQ/64);            // (16, 64)
    gemm_proj<<<ggrid, 256>>>(qkv, w_qs, qb);
    gemm_proj<<<ggrid, 256>>>(qkv, w_ks, kb);
    gemm_proj<<<ggrid, 256>>>(qkv, w_vs, vb);

    dim3 agrid(SS/64, BB*HH);            // (32, 32)
    attn_scores<<<agrid, 256>>>(qb, kb, mask, attn, mb, lb);
    attn_av<<<agrid, 256>>>(vb, attn, mb, lb, ob);

    gemm_fc<<<ggrid, 256>>>(ob, w_fc, qkv, tb);
    ln_kernel<<<NQ, 256>>>(tb, gamma, beta, out);
}

// round 4
// speedup vs baseline: 1.5917x; 1.5917x over previous
#include <cuda_runtime.h>
#include <math.h>

#define BB 2
#define SS 2048
#define HH 16
#define DK 64
#define DM 1024
#define NQ (BB*SS)
#define INV_T 0.125f
#define NEGV -1000000000.0f

// ---------------- scratch (static device allocations only) ----------------
__device__ float g_q[(size_t)BB*HH*SS*DK];
__device__ float g_k[(size_t)BB*HH*SS*DK];
__device__ float g_v[(size_t)BB*HH*SS*DK];
__device__ float g_o[(size_t)NQ*DM];
__device__ float g_tmp[(size_t)NQ*DM];
__device__ float g_m[(size_t)BB*HH*SS];
__device__ float g_l[(size_t)BB*HH*SS];
__device__ float g_attn_fb[(size_t)BB*HH*SS*SS];   // fallback if attn not in d_out

// ---------------- QKV projection GEMM: C = X @ W, stored head-major -------
// X: [4096,1024] row-major, W: [1024,1024] row-major.
// out_head[((b*H+h)*S+s)*64 + d]  with col c = h*64+d, row r = b*S+s
__global__ __launch_bounds__(256) void gemm_proj(const float* __restrict__ X,
                                                 const float* __restrict__ W,
                                                 float* __restrict__ outh)
{
    __shared__ float As[16][68];
    __shared__ float Bs[16][68];
    int tid = threadIdx.x;
    int ty = tid >> 4, tx = tid & 15;
    int row0 = blockIdx.y * 64, col0 = blockIdx.x * 64;
    float acc[4][4] = {};
    for (int k0 = 0; k0 < DM; k0 += 16) {
        {   // A tile 64x16, one float4 per thread
            int r = tid >> 2, kq = (tid & 3) * 4;
            float4 v = *(const float4*)&X[(size_t)(row0 + r)*DM + k0 + kq];
            As[kq+0][r]=v.x; As[kq+1][r]=v.y; As[kq+2][r]=v.z; As[kq+3][r]=v.w;
        }
        {   // B tile 16x64
            int kr = tid >> 4, cq = (tid & 15) * 4;
            float4 v = *(const float4*)&W[(size_t)(k0 + kr)*DM + col0 + cq];
            *(float4*)&Bs[kr][cq] = v;
        }
        __syncthreads();
        #pragma unroll
        for (int kk = 0; kk < 16; kk++) {
            float a[4], b[4];
            #pragma unroll
            for (int i = 0; i < 4; i++) a[i] = As[kk][ty*4+i];
            #pragma unroll
            for (int j = 0; j < 4; j++) b[j] = Bs[kk][tx*4+j];
            #pragma unroll
            for (int i = 0; i < 4; i++)
                #pragma unroll
                for (int j = 0; j < 4; j++) acc[i][j] = fmaf(a[i], b[j], acc[i][j]);
        }
        __syncthreads();
    }
    int c = col0 + tx*4;
    int h = c >> 6, d = c & 63;
    #pragma unroll
    for (int i = 0; i < 4; i++) {
        int r = row0 + ty*4 + i;
        int b = r / SS, s = r % SS;
        *(float4*)&outh[(((size_t)b*HH + h)*SS + s)*DK + d] =
            make_float4(acc[i][0], acc[i][1], acc[i][2], acc[i][3]);
    }
}

// ---------------- fc GEMM + residual: tmp = O @ Wfc + qkv ----------------
__global__ __launch_bounds__(256) void gemm_fc(const float* __restrict__ X,
                                               const float* __restrict__ W,
                                               const float* __restrict__ resid,
                                               float* __restrict__ out)
{
    __shared__ float As[16][68];
    __shared__ float Bs[16][68];
    int tid = threadIdx.x;
    int ty = tid >> 4, tx = tid & 15;
    int row0 = blockIdx.y * 64, col0 = blockIdx.x * 64;
    float acc[4][4] = {};
    for (int k0 = 0; k0 < DM; k0 += 16) {
        {
            int r = tid >> 2, kq = (tid & 3) * 4;
            float4 v = *(const float4*)&X[(size_t)(row0 + r)*DM + k0 + kq];
            As[kq+0][r]=v.x; As[kq+1][r]=v.y; As[kq+2][r]=v.z; As[kq+3][r]=v.w;
        }
        {
            int kr = tid >> 4, cq = (tid & 15) * 4;
            float4 v = *(const float4*)&W[(size_t)(k0 + kr)*DM + col0 + cq];
            *(float4*)&Bs[kr][cq] = v;
        }
        __syncthreads();
        #pragma unroll
        for (int kk = 0; kk < 16; kk++) {
            float a[4], b[4];
            #pragma unroll
            for (int i = 0; i < 4; i++) a[i] = As[kk][ty*4+i];
            #pragma unroll
            for (int j = 0; j < 4; j++) b[j] = Bs[kk][tx*4+j];
            #pragma unroll
            for (int i = 0; i < 4; i++)
                #pragma unroll
                for (int j = 0; j < 4; j++) acc[i][j] = fmaf(a[i], b[j], acc[i][j]);
        }
        __syncthreads();
    }
    #pragma unroll
    for (int i = 0; i < 4; i++) {
        int r = row0 + ty*4 + i;
        int c = col0 + tx*4;
        float4 rv = *(const float4*)&resid[(size_t)r*DM + c];
        *(float4*)&out[(size_t)r*DM + c] =
            make_float4(acc[i][0]+rv.x, acc[i][1]+rv.y, acc[i][2]+rv.z, acc[i][3]+rv.w);
    }
}

// -------- pass 1: raw masked/scaled scores -> attn buf; online m,l -------
__global__ __launch_bounds__(256) void attn_scores(
    const float* __restrict__ qb, const float* __restrict__ kb,
    const int* __restrict__ mask, float* __restrict__ attn,
    float* __restrict__ gm, float* __restrict__ gl)
{
    __shared__ float Qs[64][65];
    __shared__ float Ks[64][65];
    __shared__ float m_s[64];
    __shared__ float l_s[64];
    int tid = threadIdx.x;
    int ty = tid >> 4, tx = tid & 15;
    int q0 = blockIdx.x * 64;
    int bh = blockIdx.y;
    int b = bh >> 4;
    const float* qbase = qb + ((size_t)bh*SS + q0) * DK;
    #pragma unroll
    for (int k = 0; k < 4; k++) {           // Q tile, transposed: Qs[d][r]
        int p = tid + k*256;
        int r = p >> 4, d4 = (p & 15) * 4;
        float4 v = *(const float4*)&qbase[(size_t)r*DK + d4];
        Qs[d4+0][r]=v.x; Qs[d4+1][r]=v.y; Qs[d4+2][r]=v.z; Qs[d4+3][r]=v.w;
    }
    if (tid < 64) { m_s[tid] = -INFINITY; l_s[tid] = 0.0f; }
    int r0 = ty*4, c0 = tx*4;
    for (int kt = 0; kt < SS/64; kt++) {
        int k0 = kt * 64;
        __syncthreads();                    // protect Ks overwrite + m_s reads
        const float* kbase = kb + ((size_t)bh*SS + k0) * DK;
        #pragma unroll
        for (int k = 0; k < 4; k++) {       // K tile, transposed: Ks[d][c]
            int p = tid + k*256;
            int r = p >> 4, d4 = (p & 15) * 4;
            float4 v = *(const float4*)&kbase[(size_t)r*DK + d4];
            Ks[d4+0][r]=v.x; Ks[d4+1][r]=v.y; Ks[d4+2][r]=v.z; Ks[d4+3][r]=v.w;
        }
        __syncthreads();
        float acc[4][4] = {};
        #pragma unroll
        for (int d = 0; d < 64; d++) {
            float a[4], bb[4];
            #pragma unroll
            for (int i = 0; i < 4; i++) a[i] = Qs[d][r0+i];
            #pragma unroll
            for (int j = 0; j < 4; j++) bb[j] = Ks[d][c0+j];
            #pragma unroll
            for (int i = 0; i < 4; i++)
                #pragma unroll
                for (int j = 0; j < 4; j++) acc[i][j] = fmaf(a[i], bb[j], acc[i][j]);
        }
        float rm[4];
        #pragma unroll
        for (int i = 0; i < 4; i++) {       // scale + mask-replace + write raw
            int q = q0 + r0 + i;
            const int4 mv = *(const int4*)&mask[((size_t)b*SS + q)*SS + k0 + c0];
            acc[i][0] = mv.x ? acc[i][0]*INV_T : NEGV;
            acc[i][1] = mv.y ? acc[i][1]*INV_T : NEGV;
            acc[i][2] = mv.z ? acc[i][2]*INV_T : NEGV;
            acc[i][3] = mv.w ? acc[i][3]*INV_T : NEGV;
            *(float4*)&attn[((size_t)bh*SS + q)*SS + k0 + c0] =
                make_float4(acc[i][0], acc[i][1], acc[i][2], acc[i][3]);
            rm[i] = fmaxf(fmaxf(acc[i][0], acc[i][1]), fmaxf(acc[i][2], acc[i][3]));
        }
        #pragma unroll
        for (int o = 1; o < 16; o <<= 1)
            #pragma unroll
            for (int i = 0; i < 4; i++)
                rm[i] = fmaxf(rm[i], __shfl_xor_sync(0xffffffffu, rm[i], o));
        float m_old[4] = {0,0,0,0};
        if (tx == 0) {
            #pragma unroll
            for (int i = 0; i < 4; i++) {
                m_old[i] = m_s[r0+i];
                m_s[r0+i] = fmaxf(m_old[i], rm[i]);
            }
        }
        __syncthreads();
        float ps[4];
        #pragma unroll
        for (int i = 0; i < 4; i++) {
            float mr = m_s[r0+i];
            ps[i] = __expf(acc[i][0]-mr) + __expf(acc[i][1]-mr)
                  + __expf(acc[i][2]-mr) + __expf(acc[i][3]-mr);
        }
        #pragma unroll
        for (int o = 1; o < 16; o <<= 1)
            #pragma unroll
            for (int i = 0; i < 4; i++)
                ps[i] += __shfl_xor_sync(0xffffffffu, ps[i], o);
        if (tx == 0) {
            #pragma unroll
            for (int i = 0; i < 4; i++) {
                float mn = m_s[r0+i];
                l_s[r0+i] = l_s[r0+i]*__expf(m_old[i]-mn) + ps[i];
            }
        }
    }
    __syncthreads();
    if (tid < 64) {
        gm[(size_t)bh*SS + q0 + tid] = m_s[tid];
        gl[(size_t)bh*SS + q0 + tid] = l_s[tid];
    }
}

// -------- pass 2: normalize attn in place, O = P @ V (head-merged) -------
__global__ __launch_bounds__(256) void attn_av(
    const float* __restrict__ vb, float* __restrict__ attn,
    const float* __restrict__ gm, const float* __restrict__ gl,
    float* __restrict__ ob)
{
    __shared__ float Ps[64][65];
    __shared__ float Vs[64][68];
    __shared__ float m_s[64], li_s[64];
    int tid = threadIdx.x;
    int ty = tid >> 4, tx = tid & 15;
    int q0 = blockIdx.x * 64, bh = blockIdx.y;
    int b = bh >> 4, h = bh & 15;
    if (tid < 64) {
        m_s[tid]  = gm[(size_t)bh*SS + q0 + tid];
        li_s[tid] = 1.0f / gl[(size_t)bh*SS + q0 + tid];
    }
    int r0 = ty*4, c0 = tx*4;
    float acc[4][4] = {};
    for (int kt = 0; kt < SS/64; kt++) {
        int k0 = kt * 64;
        __syncthreads();
        #pragma unroll
        for (int k = 0; k < 4; k++) {       // load raw, exp-normalize, write back
            int p = tid + k*256;
            int r = p >> 4, c4 = (p & 15) * 4;
            float* ap = &attn[((size_t)bh*SS + q0 + r)*SS + k0 + c4];
            float4 v = *(float4*)ap;
            float mr = m_s[r], li = li_s[r];
            v.x = __expf(v.x - mr) * li;
            v.y = __expf(v.y - mr) * li;
            v.z = __expf(v.z - mr) * li;
            v.w = __expf(v.w - mr) * li;
            *(float4*)ap = v;
            Ps[c4+0][r]=v.x; Ps[c4+1][r]=v.y; Ps[c4+2][r]=v.z; Ps[c4+3][r]=v.w;
        }
        const float* vbase = vb + ((size_t)bh*SS + k0) * DK;
        #pragma unroll
        for (int k = 0; k < 4; k++) {       // V tile natural layout Vs[c][d]
            int p = tid + k*256;
            int r = p >> 4, d4 = (p & 15) * 4;
            *(float4*)&Vs[r][d4] = *(const float4*)&vbase[(size_t)r*DK + d4];
        }
        __syncthreads();
        #pragma unroll
        for (int c = 0; c < 64; c++) {
            float pv[4], vv[4];
            #pragma unroll
            for (int i = 0; i < 4; i++) pv[i] = Ps[c][r0+i];
            #pragma unroll
            for (int j = 0; j < 4; j++) vv[j] = Vs[c][c0+j];
            #pragma unroll
            for (int i = 0; i < 4; i++)
                #pragma unroll
                for (int j = 0; j < 4; j++) acc[i][j] = fmaf(pv[i], vv[j], acc[i][j]);
        }
    }
    #pragma unroll
    for (int i = 0; i < 4; i++) {
        int q = q0 + r0 + i;
        *(float4*)&ob[((size_t)(b*SS + q))*DM + h*DK + c0] =
            make_float4(acc[i][0], acc[i][1], acc[i][2], acc[i][3]);
    }
}

// ---------------- LayerNorm: one row (1024) per block --------------------
__global__ __launch_bounds__(256) void ln_kernel(const float* __restrict__ xin,
                                                 const float* __restrict__ gamma,
                                                 const float* __restrict__ beta,
                                                 float* __restrict__ out)
{
    __shared__ float red[8];
    __shared__ float mu_s, rs_s;
    int row = blockIdx.x, tid = threadIdx.x;
    float4 v = *(const float4*)&xin[(size_t)row*DM + tid*4];
    float s = v.x + v.y + v.z + v.w;
    #pragma unroll
    for (int o = 16; o > 0; o >>= 1) s += __shfl_down_sync(0xffffffffu, s, o);
    if ((tid & 31) == 0) red[tid >> 5] = s;
    __syncthreads();
    if (tid == 0) {
        float t = 0;
        #pragma unroll
        for (int i = 0; i < 8; i++) t += red[i];
        mu_s = t * (1.0f / DM);
    }
    __syncthreads();
    float mu = mu_s;
    float dx0 = v.x-mu, dx1 = v.y-mu, dx2 = v.z-mu, dx3 = v.w-mu;
    float s2 = dx0*dx0 + dx1*dx1 + dx2*dx2 + dx3*dx3;
    #pragma unroll
    for (int o = 16; o > 0; o >>= 1) s2 += __shfl_down_sync(0xffffffffu, s2, o);
    if ((tid & 31) == 0) red[tid >> 5] = s2;
    __syncthreads();
    if (tid == 0) {
        float t = 0;
        #pragma unroll
        for (int i = 0; i < 8; i++) t += red[i];
        rs_s = rsqrtf(t * (1.0f / DM) + 1e-6f);
    }
    __syncthreads();
    float rs = rs_s;
    float4 g  = *(const float4*)&gamma[tid*4];
    float4 bt = *(const float4*)&beta[tid*4];
    float4 o4;
    o4.x = dx0*rs*g.x + bt.x;
    o4.y = dx1*rs*g.y + bt.y;
    o4.z = dx2*rs*g.z + bt.z;
    o4.w = dx3*rs*g.w + bt.w;
    *(float4*)&out[(size_t)row*DM + tid*4] = o4;
}

// --------------------------------------------------------------------------
extern "C" void kernel_launch(void* const* d_in, const int* in_sizes, int n_in,
                              void* d_out, int out_size)
{
    const float* qkv   = (const float*)d_in[0];
    const int*   mask  = (const int*)  d_in[1];
    const float* w_qs  = (const float*)d_in[2];
    const float* w_ks  = (const float*)d_in[3];
    const float* w_vs  = (const float*)d_in[4];
    const float* w_fc  = (const float*)d_in[5];
    const float* gamma = (const float*)d_in[6];
    const float* beta  = (const float*)d_in[7];
    float* out = (float*)d_out;

    const size_t out_elems  = (size_t)NQ * DM;                 // 4,194,304
    const size_t attn_elems = (size_t)BB * HH * SS * SS;       // 134,217,728

    float *qb, *kb, *vb, *ob, *tb, *mb, *lb, *attn;
    cudaGetSymbolAddress((void**)&qb, g_q);
    cudaGetSymbolAddress((void**)&kb, g_k);
    cudaGetSymbolAddress((void**)&vb, g_v);
    cudaGetSymbolAddress((void**)&ob, g_o);
    cudaGetSymbolAddress((void**)&tb, g_tmp);
    cudaGetSymbolAddress((void**)&mb, g_m);
    cudaGetSymbolAddress((void**)&lb, g_l);
    if ((size_t)out_size >= out_elems + attn_elems) {
        attn = out + out_elems;          // attn is part of the output
    } else {
        cudaGetSymbolAddress((void**)&attn, g_attn_fb);
    }

    dim3 ggrid(DM/64, NQ/64);            // (16, 64)
    gemm_proj<<<ggrid, 256>>>(qkv, w_qs, qb);
    gemm_proj<<<ggrid, 256>>>(qkv, w_ks, kb);
    gemm_proj<<<ggrid, 256>>>(qkv, w_vs, vb);

    dim3 agrid(SS/64, BB*HH);            // (32, 32)
    attn_scores<<<agrid, 256>>>(qb, kb, mask, attn, mb, lb);
    attn_av<<<agrid, 256>>>(vb, attn, mb, lb, ob);

    gemm_fc<<<ggrid, 256>>>(ob, w_fc, qkv, tb);
    ln_kernel<<<NQ, 256>>>(tb, gamma, beta, out);
}

// round 5
// speedup vs baseline: 2.8112x; 1.7662x over previous
#include <cuda_runtime.h>
#include <cuda_bf16.h>
#include <math.h>
#include <stdint.h>

#define BB 2
#define SS 2048
#define HH 16
#define DK 64
#define DM 1024
#define NQ (BB*SS)
#define INV_T 0.125f
#define NEGV -1000000000.0f

typedef __nv_bfloat16 bf;

// ---------------- scratch (static device allocations only) ----------------
__device__ bf g_xh[(size_t)NQ*DM],  g_xl[(size_t)NQ*DM];
__device__ bf g_wqh[(size_t)DM*DM], g_wql[(size_t)DM*DM];
__device__ bf g_wkh[(size_t)DM*DM], g_wkl[(size_t)DM*DM];
__device__ bf g_wvh[(size_t)DM*DM], g_wvl[(size_t)DM*DM];
__device__ bf g_wfh[(size_t)DM*DM], g_wfl[(size_t)DM*DM];
__device__ bf g_qh[(size_t)BB*HH*SS*DK], g_ql[(size_t)BB*HH*SS*DK];
__device__ bf g_kh[(size_t)BB*HH*SS*DK], g_kl[(size_t)BB*HH*SS*DK];
__device__ bf g_vh[(size_t)BB*HH*SS*DK], g_vl[(size_t)BB*HH*SS*DK];
__device__ bf g_vTh[(size_t)BB*HH*DK*SS], g_vTl[(size_t)BB*HH*DK*SS];
__device__ bf g_oh[(size_t)NQ*DM], g_ol[(size_t)NQ*DM];
__device__ float g_tmp[(size_t)NQ*DM];
__device__ float g_m[(size_t)BB*HH*SS];
__device__ float g_l[(size_t)BB*HH*SS];
__device__ float g_attn_fb[(size_t)BB*HH*SS*SS];   // fallback if attn not in d_out

// ---------------- helpers -------------------------------------------------
__device__ __forceinline__ void mma16816(float c[4], const uint32_t a[4], const uint32_t b[2]) {
    asm volatile(
        "mma.sync.aligned.m16n8k16.row.col.f32.bf16.bf16.f32 "
        "{%0,%1,%2,%3},{%4,%5,%6,%7},{%8,%9},{%0,%1,%2,%3};\n"
        : "+f"(c[0]), "+f"(c[1]), "+f"(c[2]), "+f"(c[3])
        : "r"(a[0]), "r"(a[1]), "r"(a[2]), "r"(a[3]), "r"(b[0]), "r"(b[1]));
}

__device__ __forceinline__ void splitf(float v, bf& h, bf& l) {
    h = __float2bfloat16(v);
    l = __float2bfloat16(v - __bfloat162float(h));
}

// pack two fp32 values into bf16 hi-pair and lo-pair (as u32)
__device__ __forceinline__ void split_pair(float a, float b, uint32_t& ph, uint32_t& pl) {
    bf ha, hb, la, lb;
    splitf(a, ha, la);
    splitf(b, hb, lb);
    ph = (uint32_t)__bfloat16_as_ushort(ha) | ((uint32_t)__bfloat16_as_ushort(hb) << 16);
    pl = (uint32_t)__bfloat16_as_ushort(la) | ((uint32_t)__bfloat16_as_ushort(lb) << 16);
}

// ---------------- prep: split X into bf16 hi/lo ---------------------------
__global__ __launch_bounds__(256) void k_split(const float* __restrict__ in,
                                               bf* __restrict__ hi, bf* __restrict__ lo)
{
    int i = blockIdx.x * 256 + threadIdx.x;          // float4 index, grid exact
    float4 v = ((const float4*)in)[i];
    uint32_t h01, l01, h23, l23;
    split_pair(v.x, v.y, h01, l01);
    split_pair(v.z, v.w, h23, l23);
    ((uint2*)hi)[i] = make_uint2(h01, h23);
    ((uint2*)lo)[i] = make_uint2(l01, l23);
}

// ---------------- prep: transpose + split W: W[k][n] -> T[n][k] ----------
__global__ __launch_bounds__(256) void k_wT(const float* __restrict__ W,
                                            bf* __restrict__ Th, bf* __restrict__ Tl)
{
    __shared__ bf sh[32][33], sl[32][33];
    int tx = threadIdx.x, ty = threadIdx.y;          // (32,8)
    int n0 = blockIdx.x * 32, k0 = blockIdx.y * 32;
    #pragma unroll
    for (int i = 0; i < 4; i++) {
        int k = k0 + ty + i * 8;
        float v = W[(size_t)k * DM + n0 + tx];
        splitf(v, sh[ty + i*8][tx], sl[ty + i*8][tx]);
    }
    __syncthreads();
    #pragma unroll
    for (int i = 0; i < 4; i++) {
        int n = n0 + ty + i * 8;
        Th[(size_t)n * DM + k0 + tx] = sh[tx][ty + i*8];
        Tl[(size_t)n * DM + k0 + tx] = sl[tx][ty + i*8];
    }
}

// ---------------- prep: transpose V hi/lo -> vT[bh][d][s] ----------------
__global__ __launch_bounds__(256) void k_vT(const bf* __restrict__ vh, const bf* __restrict__ vl,
                                            bf* __restrict__ vTh, bf* __restrict__ vTl)
{
    __shared__ bf th[32][33], tl[32][33];
    int tx = threadIdx.x, ty = threadIdx.y;          // (32,8)
    int s0 = blockIdx.x * 32, d0 = blockIdx.y * 32, bh = blockIdx.z;
    #pragma unroll
    for (int i = 0; i < 4; i++) {
        int s = s0 + ty + i * 8;
        th[ty + i*8][tx] = vh[((size_t)bh * SS + s) * DK + d0 + tx];
        tl[ty + i*8][tx] = vl[((size_t)bh * SS + s) * DK + d0 + tx];
    }
    __syncthreads();
    #pragma unroll
    for (int i = 0; i < 4; i++) {
        int d = d0 + ty + i * 8;
        vTh[((size_t)bh * DK + d) * SS + s0 + tx] = th[tx][ty + i*8];
        vTl[((size_t)bh * DK + d) * SS + s0 + tx] = tl[tx][ty + i*8];
    }
}

// ---------------- GEMM (split-bf16, 3 MMA terms): projections -------------
// C = X @ W -> split to head-major qh/ql.  Block: 128(M) x 64(N), K-step 32.
// A smem: [m][k] pitch 40;  B smem: [n][k] pitch 40 (B = W^T hi/lo).
__global__ __launch_bounds__(256) void gemm_proj_mma(
    const bf* __restrict__ ah_g, const bf* __restrict__ al_g,
    const bf* __restrict__ bh_g, const bf* __restrict__ bl_g,
    bf* __restrict__ ch_g, bf* __restrict__ cl_g)
{
    __shared__ bf Ah[128][40], Al[128][40], Bh[64][40], Bl[64][40];
    int tid = threadIdx.x;
    int w = tid >> 5, lane = tid & 31;
    int g = lane >> 2, t = lane & 3;
    int wm = w >> 1, wn = w & 1;                     // warp grid 4x2, tile 32x32
    int row0 = blockIdx.y * 128, col0 = blockIdx.x * 64;
    float acc[2][4][4] = {};
    for (int k0 = 0; k0 < DM; k0 += 32) {
        #pragma unroll
        for (int j = 0; j < 2; j++) {                // A tiles: 128x32
            int idx = tid + j * 256;
            int r = idx >> 2, c = (idx & 3) * 8;
            *(uint4*)&Ah[r][c] = *(const uint4*)&ah_g[(size_t)(row0 + r) * DM + k0 + c];
            *(uint4*)&Al[r][c] = *(const uint4*)&al_g[(size_t)(row0 + r) * DM + k0 + c];
        }
        {                                            // B tiles: 64x32
            int r = tid >> 2, c = (tid & 3) * 8;
            *(uint4*)&Bh[r][c] = *(const uint4*)&bh_g[(size_t)(col0 + r) * DM + k0 + c];
            *(uint4*)&Bl[r][c] = *(const uint4*)&bl_g[(size_t)(col0 + r) * DM + k0 + c];
        }
        __syncthreads();
        #pragma unroll
        for (int ks = 0; ks < 2; ks++) {
            int kc = ks * 16 + 2 * t;
            uint32_t a_h[2][4], a_l[2][4], b_h[4][2], b_l[4][2];
            #pragma unroll
            for (int mt = 0; mt < 2; mt++) {
                int m = wm * 32 + mt * 16 + g;
                a_h[mt][0] = *(uint32_t*)&Ah[m][kc];
                a_h[mt][1] = *(uint32_t*)&Ah[m + 8][kc];
                a_h[mt][2] = *(uint32_t*)&Ah[m][kc + 8];
                a_h[mt][3] = *(uint32_t*)&Ah[m + 8][kc + 8];
                a_l[mt][0] = *(uint32_t*)&Al[m][kc];
                a_l[mt][1] = *(uint32_t*)&Al[m + 8][kc];
                a_l[mt][2] = *(uint32_t*)&Al[m][kc + 8];
                a_l[mt][3] = *(uint32_t*)&Al[m + 8][kc + 8];
            }
            #pragma unroll
            for (int nt = 0; nt < 4; nt++) {
                int n = wn * 32 + nt * 8 + g;
                b_h[nt][0] = *(uint32_t*)&Bh[n][kc];
                b_h[nt][1] = *(uint32_t*)&Bh[n][kc + 8];
                b_l[nt][0] = *(uint32_t*)&Bl[n][kc];
                b_l[nt][1] = *(uint32_t*)&Bl[n][kc + 8];
            }
            #pragma unroll
            for (int mt = 0; mt < 2; mt++)
                #pragma unroll
                for (int nt = 0; nt < 4; nt++) {
                    mma16816(acc[mt][nt], a_h[mt], b_h[nt]);
                    mma16816(acc[mt][nt], a_h[mt], b_l[nt]);
                    mma16816(acc[mt][nt], a_l[mt], b_h[nt]);
                }
        }
        __syncthreads();
    }
    // epilogue: split result to bf16 hi/lo, head-major store
    #pragma unroll
    for (int mt = 0; mt < 2; mt++)
        #pragma unroll
        for (int nt = 0; nt < 4; nt++) {
            int row = row0 + wm * 32 + mt * 16 + g;
            int col = col0 + wn * 32 + nt * 8 + 2 * t;
            int h = col >> 6, d = col & 63;
            int bi = row >> 11, s = row & 2047;
            size_t base = (((size_t)bi * HH + h) * SS + s) * DK + d;
            uint32_t ph, pl;
            split_pair(acc[mt][nt][0], acc[mt][nt][1], ph, pl);
            *(uint32_t*)&ch_g[base] = ph;
            *(uint32_t*)&cl_g[base] = pl;
            size_t base8 = (((size_t)bi * HH + h) * SS + s + 8) * DK + d;
            split_pair(acc[mt][nt][2], acc[mt][nt][3], ph, pl);
            *(uint32_t*)&ch_g[base8] = ph;
            *(uint32_t*)&cl_g[base8] = pl;
        }
}

// ---------------- GEMM fc: tmp = O @ Wfc + resid (fp32 out) ---------------
__global__ __launch_bounds__(256) void gemm_fc_mma(
    const bf* __restrict__ ah_g, const bf* __restrict__ al_g,
    const bf* __restrict__ bh_g, const bf* __restrict__ bl_g,
    const float* __restrict__ resid, float* __restrict__ out)
{
    __shared__ bf Ah[128][40], Al[128][40], Bh[64][40], Bl[64][40];
    int tid = threadIdx.x;
    int w = tid >> 5, lane = tid & 31;
    int g = lane >> 2, t = lane & 3;
    int wm = w >> 1, wn = w & 1;
    int row0 = blockIdx.y * 128, col0 = blockIdx.x * 64;
    float acc[2][4][4] = {};
    for (int k0 = 0; k0 < DM; k0 += 32) {
        #pragma unroll
        for (int j = 0; j < 2; j++) {
            int idx = tid + j * 256;
            int r = idx >> 2, c = (idx & 3) * 8;
            *(uint4*)&Ah[r][c] = *(const uint4*)&ah_g[(size_t)(row0 + r) * DM + k0 + c];
            *(uint4*)&Al[r][c] = *(const uint4*)&al_g[(size_t)(row0 + r) * DM + k0 + c];
        }
        {
            int r = tid >> 2, c = (tid & 3) * 8;
            *(uint4*)&Bh[r][c] = *(const uint4*)&bh_g[(size_t)(col0 + r) * DM + k0 + c];
            *(uint4*)&Bl[r][c] = *(const uint4*)&bl_g[(size_t)(col0 + r) * DM + k0 + c];
        }
        __syncthreads();
        #pragma unroll
        for (int ks = 0; ks < 2; ks++) {
            int kc = ks * 16 + 2 * t;
            uint32_t a_h[2][4], a_l[2][4], b_h[4][2], b_l[4][2];
            #pragma unroll
            for (int mt = 0; mt < 2; mt++) {
                int m = wm * 32 + mt * 16 + g;
                a_h[mt][0] = *(uint32_t*)&Ah[m][kc];
                a_h[mt][1] = *(uint32_t*)&Ah[m + 8][kc];
                a_h[mt][2] = *(uint32_t*)&Ah[m][kc + 8];
                a_h[mt][3] = *(uint32_t*)&Ah[m + 8][kc + 8];
                a_l[mt][0] = *(uint32_t*)&Al[m][kc];
                a_l[mt][1] = *(uint32_t*)&Al[m + 8][kc];
                a_l[mt][2] = *(uint32_t*)&Al[m][kc + 8];
                a_l[mt][3] = *(uint32_t*)&Al[m + 8][kc + 8];
            }
            #pragma unroll
            for (int nt = 0; nt < 4; nt++) {
                int n = wn * 32 + nt * 8 + g;
                b_h[nt][0] = *(uint32_t*)&Bh[n][kc];
                b_h[nt][1] = *(uint32_t*)&Bh[n][kc + 8];
                b_l[nt][0] = *(uint32_t*)&Bl[n][kc];
                b_l[nt][1] = *(uint32_t*)&Bl[n][kc + 8];
            }
            #pragma unroll
            for (int mt = 0; mt < 2; mt++)
                #pragma unroll
                for (int nt = 0; nt < 4; nt++) {
                    mma16816(acc[mt][nt], a_h[mt], b_h[nt]);
                    mma16816(acc[mt][nt], a_h[mt], b_l[nt]);
                    mma16816(acc[mt][nt], a_l[mt], b_h[nt]);
                }
        }
        __syncthreads();
    }
    #pragma unroll
    for (int mt = 0; mt < 2; mt++)
        #pragma unroll
        for (int nt = 0; nt < 4; nt++) {
            int row = row0 + wm * 32 + mt * 16 + g;
            int col = col0 + wn * 32 + nt * 8 + 2 * t;
            float2 rv = *(const float2*)&resid[(size_t)row * DM + col];
            *(float2*)&out[(size_t)row * DM + col] =
                make_float2(acc[mt][nt][0] + rv.x, acc[mt][nt][1] + rv.y);
            rv = *(const float2*)&resid[(size_t)(row + 8) * DM + col];
            *(float2*)&out[(size_t)(row + 8) * DM + col] =
                make_float2(acc[mt][nt][2] + rv.x, acc[mt][nt][3] + rv.y);
        }
}

// ------- pass 1: S = QK^T/8, mask, raw -> attn, online m/l (MMA) ---------
// Block: 64 q x 64 keys per iter (32 iters). 8 warps: 2(q) x 4(key), 32x16.
__global__ __launch_bounds__(256) void attn_scores_mma(
    const bf* __restrict__ qh, const bf* __restrict__ ql,
    const bf* __restrict__ kh, const bf* __restrict__ kl,
    const int* __restrict__ mask, float* __restrict__ attn,
    float* __restrict__ gm, float* __restrict__ gl)
{
    __shared__ bf Qh[64][72], Ql[64][72], Kh[64][72], Kl[64][72];
    __shared__ float red[4][64];
    __shared__ float m_s[64], l_s[64], mold[64];
    int tid = threadIdx.x;
    int w = tid >> 5, lane = tid & 31;
    int g = lane >> 2, t = lane & 3;
    int wq = w >> 2, wk = w & 3;                     // 2 x 4
    int q0 = blockIdx.x * 64, bh = blockIdx.y, b = bh >> 4;
    const bf* qhb = qh + ((size_t)bh * SS + q0) * DK;
    const bf* qlb = ql + ((size_t)bh * SS + q0) * DK;
    #pragma unroll
    for (int j = 0; j < 2; j++) {                    // Q tile 64x64
        int idx = tid + j * 256;
        int r = idx >> 3, c = (idx & 7) * 8;
        *(uint4*)&Qh[r][c] = *(const uint4*)&qhb[(size_t)r * DK + c];
        *(uint4*)&Ql[r][c] = *(const uint4*)&qlb[(size_t)r * DK + c];
    }
    if (tid < 64) { m_s[tid] = -INFINITY; l_s[tid] = 0.0f; }

    for (int kt = 0; kt < 32; kt++) {
        int k0 = kt * 64;
        __syncthreads();                             // prior-iter reads done
        const bf* khb = kh + ((size_t)bh * SS + k0) * DK;
        const bf* klb = kl + ((size_t)bh * SS + k0) * DK;
        #pragma unroll
        for (int j = 0; j < 2; j++) {                // K tile 64x64
            int idx = tid + j * 256;
            int r = idx >> 3, c = (idx & 7) * 8;
            *(uint4*)&Kh[r][c] = *(const uint4*)&khb[(size_t)r * DK + c];
            *(uint4*)&Kl[r][c] = *(const uint4*)&klb[(size_t)r * DK + c];
        }
        __syncthreads();
        float acc[2][2][4] = {};
        #pragma unroll
        for (int ks = 0; ks < 4; ks++) {             // d = 64 = 4 x k16
            int kc = ks * 16 + 2 * t;
            uint32_t a_h[2][4], a_l[2][4], b_h[2][2], b_l[2][2];
            #pragma unroll
            for (int mt = 0; mt < 2; mt++) {
                int m = wq * 32 + mt * 16 + g;
                a_h[mt][0] = *(uint32_t*)&Qh[m][kc];
                a_h[mt][1] = *(uint32_t*)&Qh[m + 8][kc];
                a_h[mt][2] = *(uint32_t*)&Qh[m][kc + 8];
                a_h[mt][3] = *(uint32_t*)&Qh[m + 8][kc + 8];
                a_l[mt][0] = *(uint32_t*)&Ql[m][kc];
                a_l[mt][1] = *(uint32_t*)&Ql[m + 8][kc];
                a_l[mt][2] = *(uint32_t*)&Ql[m][kc + 8];
                a_l[mt][3] = *(uint32_t*)&Ql[m + 8][kc + 8];
            }
            #pragma unroll
            for (int nt = 0; nt < 2; nt++) {
                int n = wk * 16 + nt * 8 + g;
                b_h[nt][0] = *(uint32_t*)&Kh[n][kc];
                b_h[nt][1] = *(uint32_t*)&Kh[n][kc + 8];
                b_l[nt][0] = *(uint32_t*)&Kl[n][kc];
                b_l[nt][1] = *(uint32_t*)&Kl[n][kc + 8];
            }
            #pragma unroll
            for (int mt = 0; mt < 2; mt++)
                #pragma unroll
                for (int nt = 0; nt < 2; nt++) {
                    mma16816(acc[mt][nt], a_h[mt], b_h[nt]);
                    mma16816(acc[mt][nt], a_h[mt], b_l[nt]);
                    mma16816(acc[mt][nt], a_l[mt], b_h[nt]);
                }
        }
        // scale + mask + raw store + row max
        float rmax[2][2];
        rmax[0][0] = rmax[0][1] = rmax[1][0] = rmax[1][1] = -INFINITY;
        #pragma unroll
        for (int mt = 0; mt < 2; mt++) {
            int q = q0 + wq * 32 + mt * 16 + g;
            #pragma unroll
            for (int nt = 0; nt < 2; nt++) {
                int col = k0 + wk * 16 + nt * 8 + 2 * t;
                int2 m0 = *(const int2*)&mask[((size_t)(b * SS + q)) * SS + col];
                int2 m1 = *(const int2*)&mask[((size_t)(b * SS + q + 8)) * SS + col];
                float s0 = m0.x ? acc[mt][nt][0] * INV_T : NEGV;
                float s1 = m0.y ? acc[mt][nt][1] * INV_T : NEGV;
                float s2 = m1.x ? acc[mt][nt][2] * INV_T : NEGV;
                float s3 = m1.y ? acc[mt][nt][3] * INV_T : NEGV;
                *(float2*)&attn[((size_t)bh * SS + q) * SS + col]     = make_float2(s0, s1);
                *(float2*)&attn[((size_t)bh * SS + q + 8) * SS + col] = make_float2(s2, s3);
                acc[mt][nt][0] = s0; acc[mt][nt][1] = s1;
                acc[mt][nt][2] = s2; acc[mt][nt][3] = s3;
                rmax[mt][0] = fmaxf(rmax[mt][0], fmaxf(s0, s1));
                rmax[mt][1] = fmaxf(rmax[mt][1], fmaxf(s2, s3));
            }
        }
        #pragma unroll
        for (int o = 1; o < 4; o <<= 1) {
            #pragma unroll
            for (int mt = 0; mt < 2; mt++) {
                rmax[mt][0] = fmaxf(rmax[mt][0], __shfl_xor_sync(0xffffffffu, rmax[mt][0], o));
                rmax[mt][1] = fmaxf(rmax[mt][1], __shfl_xor_sync(0xffffffffu, rmax[mt][1], o));
            }
        }
        if (t == 0) {
            #pragma unroll
            for (int mt = 0; mt < 2; mt++) {
                red[wk][wq * 32 + mt * 16 + g]     = rmax[mt][0];
                red[wk][wq * 32 + mt * 16 + g + 8] = rmax[mt][1];
            }
        }
        __syncthreads();
        if (tid < 64) {
            float mo = m_s[tid];
            float mn = fmaxf(fmaxf(red[0][tid], red[1][tid]), fmaxf(red[2][tid], red[3][tid]));
            mn = fmaxf(mn, mo);
            mold[tid] = mo;
            m_s[tid] = mn;
        }
        __syncthreads();
        float psum[2][2] = {};
        #pragma unroll
        for (int mt = 0; mt < 2; mt++) {
            int lr = wq * 32 + mt * 16 + g;
            float mr0 = m_s[lr], mr1 = m_s[lr + 8];
            #pragma unroll
            for (int nt = 0; nt < 2; nt++) {
                psum[mt][0] += __expf(acc[mt][nt][0] - mr0) + __expf(acc[mt][nt][1] - mr0);
                psum[mt][1] += __expf(acc[mt][nt][2] - mr1) + __expf(acc[mt][nt][3] - mr1);
            }
        }
        #pragma unroll
        for (int o = 1; o < 4; o <<= 1) {
            #pragma unroll
            for (int mt = 0; mt < 2; mt++) {
                psum[mt][0] += __shfl_xor_sync(0xffffffffu, psum[mt][0], o);
                psum[mt][1] += __shfl_xor_sync(0xffffffffu, psum[mt][1], o);
            }
        }
        if (t == 0) {
            #pragma unroll
            for (int mt = 0; mt < 2; mt++) {
                red[wk][wq * 32 + mt * 16 + g]     = psum[mt][0];
                red[wk][wq * 32 + mt * 16 + g + 8] = psum[mt][1];
            }
        }
        __syncthreads();
        if (tid < 64) {
            l_s[tid] = l_s[tid] * __expf(mold[tid] - m_s[tid])
                     + red[0][tid] + red[1][tid] + red[2][tid] + red[3][tid];
        }
    }
    __syncthreads();
    if (tid < 64) {
        gm[(size_t)bh * SS + q0 + tid] = m_s[tid];
        gl[(size_t)bh * SS + q0 + tid] = l_s[tid];
    }
}

// ------- pass 2: normalize attn in place; O = P @ V (MMA) ----------------
// Block: 64 q x 64 d. 8 warps: 2(q) x 4(d), warp 32x16. 32 key iters of 64.
__global__ __launch_bounds__(256) void attn_av_mma(
    const bf* __restrict__ vTh, const bf* __restrict__ vTl,
    float* __restrict__ attn,
    const float* __restrict__ gm, const float* __restrict__ gl,
    bf* __restrict__ oh, bf* __restrict__ ol)
{
    __shared__ bf Ph[64][72], Pl[64][72], Vh[64][72], Vl[64][72];
    __shared__ float m_s[64], li_s[64];
    int tid = threadIdx.x;
    int w = tid >> 5, lane = tid & 31;
    int g = lane >> 2, t = lane & 3;
    int wq = w >> 2, wd = w & 3;
    int q0 = blockIdx.x * 64, bh = blockIdx.y;
    int b = bh >> 4, h = bh & 15;
    if (tid < 64) {
        m_s[tid]  = gm[(size_t)bh * SS + q0 + tid];
        li_s[tid] = 1.0f / gl[(size_t)bh * SS + q0 + tid];
    }
    float acc[2][2][4] = {};
    __syncthreads();
    for (int kt = 0; kt < 32; kt++) {
        int k0 = kt * 64;
        __syncthreads();                             // prior-iter frag reads done
        // load + normalize P tile (64x64 fp32), write back, split to smem
        #pragma unroll
        for (int j = 0; j < 4; j++) {
            int idx = tid + j * 256;
            int r = idx >> 4, c4 = (idx & 15) * 4;
            float* ap = &attn[((size_t)bh * SS + q0 + r) * SS + k0 + c4];
            float4 v = *(float4*)ap;
            float mr = m_s[r], li = li_s[r];
            float p0 = __expf(v.x - mr) * li;
            float p1 = __expf(v.y - mr) * li;
            float p2 = __expf(v.z - mr) * li;
            float p3 = __expf(v.w - mr) * li;
            *(float4*)ap = make_float4(p0, p1, p2, p3);
            uint32_t h01, l01, h23, l23;
            split_pair(p0, p1, h01, l01);
            split_pair(p2, p3, h23, l23);
            *(uint2*)&Ph[r][c4] = make_uint2(h01, h23);
            *(uint2*)&Pl[r][c4] = make_uint2(l01, l23);
        }
        #pragma unroll
        for (int j = 0; j < 2; j++) {                // V^T tile: 64 d x 64 keys
            int idx = tid + j * 256;
            int r = idx >> 3, c = (idx & 7) * 8;
            *(uint4*)&Vh[r][c] = *(const uint4*)&vTh[((size_t)bh * DK + r) * SS + k0 + c];
            *(uint4*)&Vl[r][c] = *(const uint4*)&vTl[((size_t)bh * DK + r) * SS + k0 + c];
        }
        __syncthreads();
        #pragma unroll
        for (int ks = 0; ks < 4; ks++) {
            int kc = ks * 16 + 2 * t;
            uint32_t a_h[2][4], a_l[2][4], b_h[2][2], b_l[2][2];
            #pragma unroll
            for (int mt = 0; mt < 2; mt++) {
                int m = wq * 32 + mt * 16 + g;
                a_h[mt][0] = *(uint32_t*)&Ph[m][kc];
                a_h[mt][1] = *(uint32_t*)&Ph[m + 8][kc];
                a_h[mt][2] = *(uint32_t*)&Ph[m][kc + 8];
                a_h[mt][3] = *(uint32_t*)&Ph[m + 8][kc + 8];
                a_l[mt][0] = *(uint32_t*)&Pl[m][kc];
                a_l[mt][1] = *(uint32_t*)&Pl[m + 8][kc];
                a_l[mt][2] = *(uint32_t*)&Pl[m][kc + 8];
                a_l[mt][3] = *(uint32_t*)&Pl[m + 8][kc + 8];
            }
            #pragma unroll
            for (int nt = 0; nt < 2; nt++) {
                int n = wd * 16 + nt * 8 + g;
                b_h[nt][0] = *(uint32_t*)&Vh[n][kc];
                b_h[nt][1] = *(uint32_t*)&Vh[n][kc + 8];
                b_l[nt][0] = *(uint32_t*)&Vl[n][kc];
                b_l[nt][1] = *(uint32_t*)&Vl[n][kc + 8];
            }
            #pragma unroll
            for (int mt = 0; mt < 2; mt++)
                #pragma unroll
                for (int nt = 0; nt < 2; nt++) {
                    mma16816(acc[mt][nt], a_h[mt], b_h[nt]);
                    mma16816(acc[mt][nt], a_h[mt], b_l[nt]);
                    mma16816(acc[mt][nt], a_l[mt], b_h[nt]);
                }
        }
    }
    // epilogue: split O to bf16 hi/lo, merged-head layout [b][s][h*64+d]
    #pragma unroll
    for (int mt = 0; mt < 2; mt++)
        #pragma unroll
        for (int nt = 0; nt < 2; nt++) {
            int sg = q0 + wq * 32 + mt * 16 + g;
            int dcol = wd * 16 + nt * 8 + 2 * t;
            size_t base = ((size_t)(b * SS + sg)) * DM + h * DK + dcol;
            uint32_t ph, pl;
            split_pair(acc[mt][nt][0], acc[mt][nt][1], ph, pl);
            *(uint32_t*)&oh[base] = ph;
            *(uint32_t*)&ol[base] = pl;
            size_t base8 = ((size_t)(b * SS + sg + 8)) * DM + h * DK + dcol;
            split_pair(acc[mt][nt][2], acc[mt][nt][3], ph, pl);
            *(uint32_t*)&oh[base8] = ph;
            *(uint32_t*)&ol[base8] = pl;
        }
}

// ---------------- LayerNorm: one row (1024) per block --------------------
__global__ __launch_bounds__(256) void ln_kernel(const float* __restrict__ xin,
                                                 const float* __restrict__ gamma,
                                                 const float* __restrict__ beta,
                                                 float* __restrict__ out)
{
    __shared__ float red[8];
    __shared__ float mu_s, rs_s;
    int row = blockIdx.x, tid = threadIdx.x;
    float4 v = *(const float4*)&xin[(size_t)row * DM + tid * 4];
    float s = v.x + v.y + v.z + v.w;
    #pragma unroll
    for (int o = 16; o > 0; o >>= 1) s += __shfl_down_sync(0xffffffffu, s, o);
    if ((tid & 31) == 0) red[tid >> 5] = s;
    __syncthreads();
    if (tid == 0) {
        float tt = 0;
        #pragma unroll
        for (int i = 0; i < 8; i++) tt += red[i];
        mu_s = tt * (1.0f / DM);
    }
    __syncthreads();
    float mu = mu_s;
    float dx0 = v.x - mu, dx1 = v.y - mu, dx2 = v.z - mu, dx3 = v.w - mu;
    float s2 = dx0*dx0 + dx1*dx1 + dx2*dx2 + dx3*dx3;
    #pragma unroll
    for (int o = 16; o > 0; o >>= 1) s2 += __shfl_down_sync(0xffffffffu, s2, o);
    if ((tid & 31) == 0) red[tid >> 5] = s2;
    __syncthreads();
    if (tid == 0) {
        float tt = 0;
        #pragma unroll
        for (int i = 0; i < 8; i++) tt += red[i];
        rs_s = rsqrtf(tt * (1.0f / DM) + 1e-6f);
    }
    __syncthreads();
    float rs = rs_s;
    float4 gmv = *(const float4*)&gamma[tid * 4];
    float4 btv = *(const float4*)&beta[tid * 4];
    float4 o4;
    o4.x = dx0 * rs * gmv.x + btv.x;
    o4.y = dx1 * rs * gmv.y + btv.y;
    o4.z = dx2 * rs * gmv.z + btv.z;
    o4.w = dx3 * rs * gmv.w + btv.w;
    *(float4*)&out[(size_t)row * DM + tid * 4] = o4;
}

// --------------------------------------------------------------------------
extern "C" void kernel_launch(void* const* d_in, const int* in_sizes, int n_in,
                              void* d_out, int out_size)
{
    const float* qkv   = (const float*)d_in[0];
    const int*   mask  = (const int*)  d_in[1];
    const float* w_qs  = (const float*)d_in[2];
    const float* w_ks  = (const float*)d_in[3];
    const float* w_vs  = (const float*)d_in[4];
    const float* w_fc  = (const float*)d_in[5];
    const float* gamma = (const float*)d_in[6];
    const float* beta  = (const float*)d_in[7];
    float* out = (float*)d_out;

    const size_t out_elems  = (size_t)NQ * DM;
    const size_t attn_elems = (size_t)BB * HH * SS * SS;

    bf *xh, *xl, *wqh, *wql, *wkh, *wkl, *wvh, *wvl, *wfh, *wfl;
    bf *qh, *ql, *kh, *kl, *vh, *vl, *vth, *vtl, *oh, *ol;
    float *tb, *mb, *lb, *attn;
    cudaGetSymbolAddress((void**)&xh,  g_xh);  cudaGetSymbolAddress((void**)&xl,  g_xl);
    cudaGetSymbolAddress((void**)&wqh, g_wqh); cudaGetSymbolAddress((void**)&wql, g_wql);
    cudaGetSymbolAddress((void**)&wkh, g_wkh); cudaGetSymbolAddress((void**)&wkl, g_wkl);
    cudaGetSymbolAddress((void**)&wvh, g_wvh); cudaGetSymbolAddress((void**)&wvl, g_wvl);
    cudaGetSymbolAddress((void**)&wfh, g_wfh); cudaGetSymbolAddress((void**)&wfl, g_wfl);
    cudaGetSymbolAddress((void**)&qh,  g_qh);  cudaGetSymbolAddress((void**)&ql,  g_ql);
    cudaGetSymbolAddress((void**)&kh,  g_kh);  cudaGetSymbolAddress((void**)&kl,  g_kl);
    cudaGetSymbolAddress((void**)&vh,  g_vh);  cudaGetSymbolAddress((void**)&vl,  g_vl);
    cudaGetSymbolAddress((void**)&vth, g_vTh); cudaGetSymbolAddress((void**)&vtl, g_vTl);
    cudaGetSymbolAddress((void**)&oh,  g_oh);  cudaGetSymbolAddress((void**)&ol,  g_ol);
    cudaGetSymbolAddress((void**)&tb,  g_tmp);
    cudaGetSymbolAddress((void**)&mb,  g_m);
    cudaGetSymbolAddress((void**)&lb,  g_l);
    if ((size_t)out_size >= out_elems + attn_elems) {
        attn = out + out_elems;
    } else {
        cudaGetSymbolAddress((void**)&attn, g_attn_fb);
    }

    // prep: split X, transpose+split weights
    k_split<<<4096, 256>>>(qkv, xh, xl);
    dim3 wtg(32, 32), wtb(32, 8);
    k_wT<<<wtg, wtb>>>(w_qs, wqh, wql);
    k_wT<<<wtg, wtb>>>(w_ks, wkh, wkl);
    k_wT<<<wtg, wtb>>>(w_vs, wvh, wvl);
    k_wT<<<wtg, wtb>>>(w_fc, wfh, wfl);

    // projections (tensor-core)
    dim3 ggrid(DM / 64, NQ / 128);       // (16, 32)
    gemm_proj_mma<<<ggrid, 256>>>(xh, xl, wqh, wql, qh, ql);
    gemm_proj_mma<<<ggrid, 256>>>(xh, xl, wkh, wkl, kh, kl);
    gemm_proj_mma<<<ggrid, 256>>>(xh, xl, wvh, wvl, vh, vl);
    k_vT<<<dim3(SS / 32, DK / 32, BB * HH), wtb>>>(vh, vl, vth, vtl);

    // attention (tensor-core)
    dim3 agrid(SS / 64, BB * HH);        // (32, 32)
    attn_scores_mma<<<agrid, 256>>>(qh, ql, kh, kl, mask, attn, mb, lb);
    attn_av_mma<<<agrid, 256>>>(vth, vtl, attn, mb, lb, oh, ol);

    // output projection + residual, then LayerNorm
    gemm_fc_mma<<<ggrid, 256>>>(oh, ol, wfh, wfl, qkv, tb);
    ln_kernel<<<NQ, 256>>>(tb, gamma, beta, out);
}